// round 4
// baseline (speedup 1.0000x reference)
#include <cuda_runtime.h>
#include <math.h>
#include <stdint.h>

#define B_   16
#define CLEN 4096
#define QLEN 512
#define H    256

// ---- scratch (device globals; allocation-free) ----
__device__ __align__(128) float g_S [(size_t)B_*CLEN*QLEN];  // probs (tf32-rounded fp32)
__device__ __align__(128) float g_qs[B_*QLEN*H];             // rtf(q*w_cq)
__device__ __align__(128) float g_qr[B_*QLEN*H];             // rtf(q)
__device__ float g_u[B_*CLEN];
__device__ float g_v[B_*QLEN];
__device__ float g_m[B_*CLEN];
__device__ float g_bm[B_];
__device__ float g_Z[B_];
__device__ float g_part[B_*32*H];
__device__ float g_q2c[B_*H];

__device__ __forceinline__ float rtf(float x){
    uint32_t u; asm("cvt.rna.tf32.f32 %0, %1;" : "=r"(u) : "f"(x));
    return __uint_as_float(u);
}

#define CPA16(s,g)  asm volatile("cp.async.cg.shared.global [%0], [%1], 16;\n" :: "r"(s), "l"(g))
#define CPCOMMIT()  asm volatile("cp.async.commit_group;\n")
#define CPWAIT0()   asm volatile("cp.async.wait_group 0;\n")
#define CPWAIT1()   asm volatile("cp.async.wait_group 1;\n")

__device__ __forceinline__ void mma_tf32(float* d, const uint32_t* a, const uint32_t* b){
    asm volatile("mma.sync.aligned.m16n8k8.row.col.f32.tf32.tf32.f32 "
        "{%0,%1,%2,%3}, {%4,%5,%6,%7}, {%8,%9}, {%0,%1,%2,%3};"
        : "+f"(d[0]),"+f"(d[1]),"+f"(d[2]),"+f"(d[3])
        : "r"(a[0]),"r"(a[1]),"r"(a[2]),"r"(a[3]), "r"(b[0]),"r"(b[1]));
}

// ---------------------------------------------------------------------------
// prep: g_qs = rtf(q*w_cq), g_qr = rtf(q)   (c is fed raw; HW truncates)
// ---------------------------------------------------------------------------
__global__ __launch_bounds__(256) void prep_q(
    const float4* __restrict__ q, const float4* __restrict__ w)
{
    size_t i = (size_t)blockIdx.x * 256 + threadIdx.x;
    if (i >= (size_t)B_*QLEN*(H/4)) return;
    float4 x = q[i];
    float4 wv = w[i & (H/4 - 1)];
    ((float4*)g_qr)[i] = make_float4(rtf(x.x), rtf(x.y), rtf(x.z), rtf(x.w));
    ((float4*)g_qs)[i] = make_float4(rtf(x.x*wv.x), rtf(x.y*wv.y),
                                     rtf(x.z*wv.z), rtf(x.w*wv.w));
}

// ---------------------------------------------------------------------------
// uv: u[b,i] = c_i.w_c + b_c ; v[b,j] = q_j.w_q + b_q + b_cq   (warp/row)
// ---------------------------------------------------------------------------
__global__ __launch_bounds__(256) void uv_kernel(
    const float* __restrict__ c, const float* __restrict__ q,
    const float* __restrict__ w_c, const float* __restrict__ b_c,
    const float* __restrict__ w_q, const float* __restrict__ b_q,
    const float* __restrict__ b_cq)
{
    int warp = (blockIdx.x * blockDim.x + threadIdx.x) >> 5;
    int lane = threadIdx.x & 31;
    if (warp < B_ * CLEN) {
        const float* row = c + (size_t)warp * H;
        float s = 0.f;
        #pragma unroll
        for (int t = 0; t < H/32; t++) s = fmaf(row[lane + t*32], w_c[lane + t*32], s);
        #pragma unroll
        for (int o = 16; o; o >>= 1) s += __shfl_xor_sync(0xffffffffu, s, o);
        if (lane == 0) g_u[warp] = s + b_c[0];
    } else {
        int r = warp - B_ * CLEN;
        if (r < B_ * QLEN) {
            const float* row = q + (size_t)r * H;
            float s = 0.f;
            #pragma unroll
            for (int t = 0; t < H/32; t++) s = fmaf(row[lane + t*32], w_q[lane + t*32], s);
            #pragma unroll
            for (int o = 16; o; o >>= 1) s += __shfl_xor_sync(0xffffffffu, s, o);
            if (lane == 0) g_v[r] = s + b_q[0] + b_cq[0];
        }
    }
}

// ---------------------------------------------------------------------------
// FUSED GEMM1 + row softmax.
// CTA: M=64 rows x N=512 (full row), K=256. 256 threads, 8 warps (wm 2 x wn 4).
// N processed in 4 chunks of 128; acc[4][2][4][4] = 128 regs/thread.
// Epilogue: +v, row-max (quad shfl + smem cross-warp), exp, sum, scale,
// store probs (tf32-rounded) to g_S; g_m = rowmax + u.
// ---------------------------------------------------------------------------
__global__ __launch_bounds__(256,1) void gemm1_softmax(const float* __restrict__ c)
{
    __shared__ float As[2][64][20];    // [stage][m][k]
    __shared__ float Bs[2][128][20];   // [stage][n][k]
    __shared__ float vsm[QLEN];
    __shared__ float usm[64];
    __shared__ float smax[64][4];
    __shared__ float ssum[64][4];

    const int b  = blockIdx.y, m0 = blockIdx.x * 64;
    const int tid = threadIdx.x;
    const int lane = tid & 31, wid = tid >> 5;
    const int wm = wid >> 2, wn = wid & 3;       // 2 x 4
    const int gid = lane >> 2, tig = lane & 3;
    const int alr = tid >> 2, alk = (tid & 3) * 4;   // A copy: 64 rows x 16k
    const int blr = tid >> 1, blk = (tid & 1) * 8;   // B copy: 128 rows x 16k

    // preload v, u
    if (tid < 64) usm[tid] = g_u[b*CLEN + m0 + tid];
    for (int i = tid; i < QLEN; i += 256) vsm[i] = g_v[b*QLEN + i];

    const uint32_t sA0 = (uint32_t)__cvta_generic_to_shared(&As[0][alr][alk]);
    const uint32_t sB0 = (uint32_t)__cvta_generic_to_shared(&Bs[0][blr][blk]);
    const float* Ag = c + ((size_t)(b*CLEN + m0 + alr))*H + alk;

    float acc[4][2][4][4];
    #pragma unroll
    for (int nc = 0; nc < 4; nc++)
        #pragma unroll
        for (int mt = 0; mt < 2; mt++)
            #pragma unroll
            for (int nt = 0; nt < 4; nt++)
                #pragma unroll
                for (int r = 0; r < 4; r++) acc[nc][mt][nt][r] = 0.f;

    for (int nc = 0; nc < 4; nc++) {
        const float* Bg = g_qs + ((size_t)(b*QLEN + nc*128 + blr))*H + blk;
        // stage 0
        CPA16(sA0, Ag);
        CPA16(sB0, Bg); CPA16(sB0 + 16u, Bg + 4);
        CPCOMMIT();
        for (int kt = 0; kt < 16; kt++) {
            const int st = kt & 1;
            if (kt < 15) {
                const int kc = (kt + 1) * 16;
                CPA16(sA0 + (st^1)*5120u, Ag + kc);
                CPA16(sB0 + (st^1)*10240u, Bg + kc);
                CPA16(sB0 + (st^1)*10240u + 16u, Bg + kc + 4);
                CPCOMMIT();
                CPWAIT1();
            } else {
                CPWAIT0();
            }
            __syncthreads();
            #pragma unroll
            for (int kk = 0; kk < 16; kk += 8) {
                uint32_t a[2][4], bf[4][2];
                #pragma unroll
                for (int mt = 0; mt < 2; mt++) {
                    int m = wm*32 + mt*16 + gid;
                    a[mt][0] = __float_as_uint(As[st][m    ][kk+tig  ]);
                    a[mt][1] = __float_as_uint(As[st][m + 8][kk+tig  ]);
                    a[mt][2] = __float_as_uint(As[st][m    ][kk+tig+4]);
                    a[mt][3] = __float_as_uint(As[st][m + 8][kk+tig+4]);
                }
                #pragma unroll
                for (int nt = 0; nt < 4; nt++) {
                    int n = wn*32 + nt*8 + gid;
                    bf[nt][0] = __float_as_uint(Bs[st][n][kk+tig  ]);
                    bf[nt][1] = __float_as_uint(Bs[st][n][kk+tig+4]);
                }
                #pragma unroll
                for (int mt = 0; mt < 2; mt++)
                    #pragma unroll
                    for (int nt = 0; nt < 4; nt++)
                        mma_tf32(acc[nc][mt][nt], a[mt], bf[nt]);
            }
            __syncthreads();
        }
    }

    // ---- epilogue: softmax over the 512 cols of each of 64 rows ----
    // add v
    #pragma unroll
    for (int nc = 0; nc < 4; nc++)
        #pragma unroll
        for (int nt = 0; nt < 4; nt++) {
            int col = nc*128 + wn*32 + nt*8 + tig*2;
            float v0 = vsm[col], v1 = vsm[col+1];
            #pragma unroll
            for (int mt = 0; mt < 2; mt++) {
                acc[nc][mt][nt][0] += v0; acc[nc][mt][nt][1] += v1;
                acc[nc][mt][nt][2] += v0; acc[nc][mt][nt][3] += v1;
            }
        }

    // per-(mt,r) row partial max over this thread's 32 cols
    float mx[2][2];
    #pragma unroll
    for (int mt = 0; mt < 2; mt++)
        #pragma unroll
        for (int r = 0; r < 2; r++) {
            float m = -3.402823466e38f;
            #pragma unroll
            for (int nc = 0; nc < 4; nc++)
                #pragma unroll
                for (int nt = 0; nt < 4; nt++)
                    m = fmaxf(m, fmaxf(acc[nc][mt][nt][2*r], acc[nc][mt][nt][2*r+1]));
            mx[mt][r] = m;
        }
    #pragma unroll
    for (int mt = 0; mt < 2; mt++)
        #pragma unroll
        for (int r = 0; r < 2; r++) {
            mx[mt][r] = fmaxf(mx[mt][r], __shfl_xor_sync(0xffffffffu, mx[mt][r], 1));
            mx[mt][r] = fmaxf(mx[mt][r], __shfl_xor_sync(0xffffffffu, mx[mt][r], 2));
        }
    if (tig == 0) {
        #pragma unroll
        for (int mt = 0; mt < 2; mt++)
            #pragma unroll
            for (int r = 0; r < 2; r++)
                smax[wm*32 + mt*16 + gid + 8*r][wn] = mx[mt][r];
    }
    __syncthreads();
    float fm[2][2];
    #pragma unroll
    for (int mt = 0; mt < 2; mt++)
        #pragma unroll
        for (int r = 0; r < 2; r++) {
            int row = wm*32 + mt*16 + gid + 8*r;
            fm[mt][r] = fmaxf(fmaxf(smax[row][0], smax[row][1]),
                              fmaxf(smax[row][2], smax[row][3]));
        }

    // exp in place + partial sum
    float sm[2][2] = {{0.f,0.f},{0.f,0.f}};
    #pragma unroll
    for (int nc = 0; nc < 4; nc++)
        #pragma unroll
        for (int mt = 0; mt < 2; mt++)
            #pragma unroll
            for (int nt = 0; nt < 4; nt++) {
                #pragma unroll
                for (int r = 0; r < 2; r++) {
                    float e0 = __expf(acc[nc][mt][nt][2*r]   - fm[mt][r]);
                    float e1 = __expf(acc[nc][mt][nt][2*r+1] - fm[mt][r]);
                    acc[nc][mt][nt][2*r] = e0; acc[nc][mt][nt][2*r+1] = e1;
                    sm[mt][r] += e0 + e1;
                }
            }
    #pragma unroll
    for (int mt = 0; mt < 2; mt++)
        #pragma unroll
        for (int r = 0; r < 2; r++) {
            sm[mt][r] += __shfl_xor_sync(0xffffffffu, sm[mt][r], 1);
            sm[mt][r] += __shfl_xor_sync(0xffffffffu, sm[mt][r], 2);
        }
    if (tig == 0) {
        #pragma unroll
        for (int mt = 0; mt < 2; mt++)
            #pragma unroll
            for (int r = 0; r < 2; r++)
                ssum[wm*32 + mt*16 + gid + 8*r][wn] = sm[mt][r];
    }
    __syncthreads();

    #pragma unroll
    for (int mt = 0; mt < 2; mt++)
        #pragma unroll
        for (int r = 0; r < 2; r++) {
            int row = wm*32 + mt*16 + gid + 8*r;
            float Z = ssum[row][0] + ssum[row][1] + ssum[row][2] + ssum[row][3];
            float inv = 1.f / Z;
            float* p = g_S + ((size_t)(b*CLEN + m0 + row)) * QLEN;
            #pragma unroll
            for (int nc = 0; nc < 4; nc++)
                #pragma unroll
                for (int nt = 0; nt < 4; nt++) {
                    int col = nc*128 + wn*32 + nt*8 + tig*2;
                    float2 o = make_float2(rtf(acc[nc][mt][nt][2*r]   * inv),
                                           rtf(acc[nc][mt][nt][2*r+1] * inv));
                    *(float2*)&p[col] = o;
                }
            if (wn == 0 && tig == 0)
                g_m[b*CLEN + m0 + row] = fm[mt][r] + usm[row];
        }
}

// ---------------------------------------------------------------------------
// q2c: per-batch max & Z over m; 512-CTA partial sums; reduce
// ---------------------------------------------------------------------------
__global__ __launch_bounds__(256) void bmz_kernel()
{
    int b = blockIdx.x, tid = threadIdx.x;
    __shared__ float red[8];
    const float* m = g_m + b*CLEN;
    float mx = -3.402823466e38f;
    for (int i = tid; i < CLEN; i += 256) mx = fmaxf(mx, m[i]);
    #pragma unroll
    for (int o = 16; o; o >>= 1) mx = fmaxf(mx, __shfl_xor_sync(0xffffffffu, mx, o));
    if ((tid & 31) == 0) red[tid >> 5] = mx;
    __syncthreads();
    mx = red[0];
    #pragma unroll
    for (int i = 1; i < 8; i++) mx = fmaxf(mx, red[i]);
    __syncthreads();
    float s = 0.f;
    for (int i = tid; i < CLEN; i += 256) s += __expf(m[i] - mx);
    #pragma unroll
    for (int o = 16; o; o >>= 1) s += __shfl_xor_sync(0xffffffffu, s, o);
    if ((tid & 31) == 0) red[tid >> 5] = s;
    __syncthreads();
    if (tid == 0) {
        float Z = 0.f;
        #pragma unroll
        for (int i = 0; i < 8; i++) Z += red[i];
        g_bm[b] = mx; g_Z[b] = Z;
    }
}

__global__ __launch_bounds__(256) void q2c_part(const float* __restrict__ c)
{
    const int b = blockIdx.y, p = blockIdx.x, tid = threadIdx.x;
    __shared__ float w[128];
    if (tid < 128) w[tid] = __expf(g_m[b*CLEN + p*128 + tid] - g_bm[b]);
    __syncthreads();
    const float invZ = 1.f / g_Z[b];
    const float* cb = c + ((size_t)b*CLEN + p*128)*H + tid;
    float acc = 0.f;
    #pragma unroll 8
    for (int i = 0; i < 128; i++) acc = fmaf(w[i], cb[(size_t)i*H], acc);
    g_part[(b*32 + p)*H + tid] = acc * invZ;
}

__global__ __launch_bounds__(256) void q2c_reduce()
{
    int b = blockIdx.x, d = threadIdx.x;
    float s = 0.f;
    #pragma unroll
    for (int p = 0; p < 32; p++) s += g_part[(b*32 + p)*H + d];
    g_q2c[b*H + d] = s;
}

// ---------------------------------------------------------------------------
// GEMM2 (tf32 mma): c2q = P @ q_r, fused 4-section output epilogue
// ---------------------------------------------------------------------------
__global__ __launch_bounds__(256,2) void gemm2_tc(
    const float* __restrict__ c, float* __restrict__ out)
{
    __shared__ float As[2][128][20];   // [stage][m][k]  A = probs
    __shared__ float Bs[2][16][136];   // [stage][k][n]  B = q_r
    const int b  = blockIdx.z, m0 = blockIdx.y*128, n0 = blockIdx.x*128;
    const int tid = threadIdx.x;
    const int lane = tid & 31, wid = tid >> 5;
    const int wm = wid >> 2, wn = wid & 3;
    const int gid = lane >> 2, tig = lane & 3;
    const int cm = tid >> 2, ck = (tid & 3) * 4;    // A copy
    const int bk = tid >> 4, bn = (tid & 15) * 4;   // B copy

    const float* Ag = g_S  + ((size_t)b*CLEN + m0 + cm)*QLEN + ck;
    const float* Bg = g_qr + ((size_t)b*QLEN + bk)*H + n0 + bn;
    const uint32_t sA = (uint32_t)__cvta_generic_to_shared(&As[0][cm][ck]);
    const uint32_t sB = (uint32_t)__cvta_generic_to_shared(&Bs[0][bk][bn]);

    float acc[4][4][4];
    #pragma unroll
    for (int i = 0; i < 4; i++)
        #pragma unroll
        for (int j = 0; j < 4; j++)
            #pragma unroll
            for (int r = 0; r < 4; r++) acc[i][j][r] = 0.f;

    CPA16(sA, Ag); CPA16(sA + 5120u, Ag + (size_t)64*QLEN);
    CPA16(sB, Bg); CPA16(sB + 256u, Bg + 64);
    CPCOMMIT();

    for (int i = 0; i < QLEN/16; i++) {
        const int st = i & 1;
        if (i + 1 < QLEN/16) {
            const int kc = (i+1)*16;
            const uint32_t oa = sA + (st^1)*10240u, ob = sB + (st^1)*8704u;
            CPA16(oa, Ag + kc); CPA16(oa + 5120u, Ag + (size_t)64*QLEN + kc);
            CPA16(ob, Bg + (size_t)kc*H); CPA16(ob + 256u, Bg + (size_t)kc*H + 64);
            CPCOMMIT();
            CPWAIT1();
        } else {
            CPWAIT0();
        }
        __syncthreads();
        #pragma unroll
        for (int kk = 0; kk < 16; kk += 8) {
            uint32_t a[4][4], bf[4][2];
            #pragma unroll
            for (int mt = 0; mt < 4; mt++) {
                int m = wm*64 + mt*16 + gid;
                a[mt][0] = __float_as_uint(As[st][m    ][kk+tig  ]);
                a[mt][1] = __float_as_uint(As[st][m + 8][kk+tig  ]);
                a[mt][2] = __float_as_uint(As[st][m    ][kk+tig+4]);
                a[mt][3] = __float_as_uint(As[st][m + 8][kk+tig+4]);
            }
            #pragma unroll
            for (int nt = 0; nt < 4; nt++) {
                int n = wn*32 + nt*8 + gid;
                bf[nt][0] = __float_as_uint(Bs[st][kk+tig  ][n]);
                bf[nt][1] = __float_as_uint(Bs[st][kk+tig+4][n]);
            }
            #pragma unroll
            for (int mt = 0; mt < 4; mt++)
                #pragma unroll
                for (int nt = 0; nt < 4; nt++)
                    mma_tf32(acc[mt][nt], a[mt], bf[nt]);
        }
        __syncthreads();
    }

    // fused epilogue: out = [c | c2q | c*c2q | c*q2c]
    const int nbase = n0 + wn*32;
    float2 gv[4];
    #pragma unroll
    for (int nt = 0; nt < 4; nt++)
        gv[nt] = *(const float2*)&g_q2c[b*H + nbase + nt*8 + 2*tig];
    #pragma unroll
    for (int mt = 0; mt < 4; mt++)
        #pragma unroll
        for (int r = 0; r < 2; r++) {
            int row = m0 + wm*64 + mt*16 + gid + 8*r;
            const float* crow = c + ((size_t)b*CLEN + row)*H;
            float* orow = out + ((size_t)b*CLEN + row)*(4*H);
            #pragma unroll
            for (int nt = 0; nt < 4; nt++) {
                int col = nbase + nt*8 + 2*tig;
                float2 cv = *(const float2*)&crow[col];
                float2 av = make_float2(acc[mt][nt][2*r], acc[mt][nt][2*r+1]);
                *(float2*)&orow[col]       = cv;
                *(float2*)&orow[H + col]   = av;
                *(float2*)&orow[2*H + col] = make_float2(cv.x*av.x, cv.y*av.y);
                *(float2*)&orow[3*H + col] = make_float2(cv.x*gv[nt].x, cv.y*gv[nt].y);
            }
        }
}

// ---------------------------------------------------------------------------
extern "C" void kernel_launch(void* const* d_in, const int* in_sizes, int n_in,
                              void* d_out, int out_size)
{
    const float* c    = (const float*)d_in[0];
    const float* q    = (const float*)d_in[1];
    const float* w_c  = (const float*)d_in[2];
    const float* b_c  = (const float*)d_in[3];
    const float* w_q  = (const float*)d_in[4];
    const float* b_q  = (const float*)d_in[5];
    const float* w_cq = (const float*)d_in[6];
    const float* b_cq = (const float*)d_in[7];
    float* out = (float*)d_out;

    {   // q prep (tiny)
        size_t n4 = (size_t)B_*QLEN*(H/4);
        prep_q<<<(unsigned)((n4 + 255)/256), 256>>>((const float4*)q, (const float4*)w_cq);
    }
    {   // row dots
        int warps = B_*CLEN + B_*QLEN;
        uv_kernel<<<(warps*32 + 255)/256, 256>>>(c, q, w_c, b_c, w_q, b_q, b_cq);
    }
    {   // fused S-gemm + softmax
        dim3 grid(CLEN/64, B_);
        gemm1_softmax<<<grid, 256>>>(c);
    }
    bmz_kernel<<<B_, 256>>>();
    {
        dim3 grid(32, B_);
        q2c_part<<<grid, 256>>>(c);
    }
    q2c_reduce<<<B_, 256>>>();
    {   // c2q + fused output
        dim3 grid(H/128, CLEN/128, B_);
        gemm2_tc<<<grid, 256>>>(c, out);
    }
}

// round 5
// speedup vs baseline: 1.4383x; 1.4383x over previous
#include <cuda_runtime.h>
#include <cuda_fp16.h>
#include <math.h>
#include <stdint.h>

#define B_   16
#define CLEN 4096
#define QLEN 512
#define H    256

// ---- scratch (device globals; allocation-free) ----
__device__ __align__(128) float  g_S [(size_t)B_*CLEN*QLEN];   // raw logits S
__device__ __align__(128) __half g_P [(size_t)B_*CLEN*QLEN];   // probs fp16
__device__ __align__(128) float  g_qs[B_*QLEN*H];              // rtf(q*w_cq) for gemm1
__device__ __align__(128) __half g_qt[B_*H*QLEN];              // q^T fp16 [b][d][j]
__device__ float g_u[B_*CLEN];
__device__ float g_v[B_*QLEN];
__device__ float g_m[B_*CLEN];
__device__ float g_bm[B_];
__device__ float g_Z[B_];
__device__ float g_part[B_*32*H];
__device__ float g_q2c[B_*H];

__device__ __forceinline__ float rtf(float x){
    uint32_t u; asm("cvt.rna.tf32.f32 %0, %1;" : "=r"(u) : "f"(x));
    return __uint_as_float(u);
}

#define CPA16(s,g)  asm volatile("cp.async.cg.shared.global [%0], [%1], 16;\n" :: "r"(s), "l"(g))
#define CPCOMMIT()  asm volatile("cp.async.commit_group;\n")
#define CPWAIT0()   asm volatile("cp.async.wait_group 0;\n")
#define CPWAIT1()   asm volatile("cp.async.wait_group 1;\n")

__device__ __forceinline__ void mma_tf32(float* d, const uint32_t* a, const uint32_t* b){
    asm volatile("mma.sync.aligned.m16n8k8.row.col.f32.tf32.tf32.f32 "
        "{%0,%1,%2,%3}, {%4,%5,%6,%7}, {%8,%9}, {%0,%1,%2,%3};"
        : "+f"(d[0]),"+f"(d[1]),"+f"(d[2]),"+f"(d[3])
        : "r"(a[0]),"r"(a[1]),"r"(a[2]),"r"(a[3]), "r"(b[0]),"r"(b[1]));
}
__device__ __forceinline__ void mma_f16(float* d, const uint32_t* a, const uint32_t* b){
    asm volatile("mma.sync.aligned.m16n8k16.row.col.f32.f16.f16.f32 "
        "{%0,%1,%2,%3}, {%4,%5,%6,%7}, {%8,%9}, {%0,%1,%2,%3};"
        : "+f"(d[0]),"+f"(d[1]),"+f"(d[2]),"+f"(d[3])
        : "r"(a[0]),"r"(a[1]),"r"(a[2]),"r"(a[3]), "r"(b[0]),"r"(b[1]));
}

// ---------------------------------------------------------------------------
// prep_q: g_qs = rtf(q*w_cq)
// ---------------------------------------------------------------------------
__global__ __launch_bounds__(256) void prep_q(
    const float4* __restrict__ q, const float4* __restrict__ w)
{
    size_t i = (size_t)blockIdx.x * 256 + threadIdx.x;
    if (i >= (size_t)B_*QLEN*(H/4)) return;
    float4 x = q[i];
    float4 wv = w[i & (H/4 - 1)];
    ((float4*)g_qs)[i] = make_float4(rtf(x.x*wv.x), rtf(x.y*wv.y),
                                     rtf(x.z*wv.z), rtf(x.w*wv.w));
}

// ---------------------------------------------------------------------------
// qtrans: q[b][j][d] fp32 -> g_qt[b][d][j] fp16
// ---------------------------------------------------------------------------
__global__ void qtrans_kernel(const float* __restrict__ q)
{
    __shared__ float tile[32][33];
    const int j0 = blockIdx.x * 32, d0 = blockIdx.y * 32, b = blockIdx.z;
    const int tx = threadIdx.x, ty = threadIdx.y;   // 32 x 8
    #pragma unroll
    for (int r = 0; r < 4; r++)
        tile[ty + 8*r][tx] = q[((size_t)b*QLEN + j0 + ty + 8*r)*H + d0 + tx];
    __syncthreads();
    #pragma unroll
    for (int r = 0; r < 4; r++) {
        int d = d0 + ty + 8*r, j = j0 + tx;
        g_qt[((size_t)b*H + d)*QLEN + j] = __float2half_rn(tile[tx][ty + 8*r]);
    }
}

// ---------------------------------------------------------------------------
// uv: u[b,i] = c_i.w_c + b_c ; v[b,j] = q_j.w_q + b_q + b_cq   (warp/row)
// ---------------------------------------------------------------------------
__global__ __launch_bounds__(256) void uv_kernel(
    const float* __restrict__ c, const float* __restrict__ q,
    const float* __restrict__ w_c, const float* __restrict__ b_c,
    const float* __restrict__ w_q, const float* __restrict__ b_q,
    const float* __restrict__ b_cq)
{
    int warp = (blockIdx.x * blockDim.x + threadIdx.x) >> 5;
    int lane = threadIdx.x & 31;
    if (warp < B_ * CLEN) {
        const float* row = c + (size_t)warp * H;
        float s = 0.f;
        #pragma unroll
        for (int t = 0; t < H/32; t++) s = fmaf(row[lane + t*32], w_c[lane + t*32], s);
        #pragma unroll
        for (int o = 16; o; o >>= 1) s += __shfl_xor_sync(0xffffffffu, s, o);
        if (lane == 0) g_u[warp] = s + b_c[0];
    } else {
        int r = warp - B_ * CLEN;
        if (r < B_ * QLEN) {
            const float* row = q + (size_t)r * H;
            float s = 0.f;
            #pragma unroll
            for (int t = 0; t < H/32; t++) s = fmaf(row[lane + t*32], w_q[lane + t*32], s);
            #pragma unroll
            for (int o = 16; o; o >>= 1) s += __shfl_xor_sync(0xffffffffu, s, o);
            if (lane == 0) g_v[r] = s + b_q[0] + b_cq[0];
        }
    }
}

// ---------------------------------------------------------------------------
// GEMM1 (tf32 mma): S[b,i,j] = sum_d c[b,i,d]*qs[b,j,d] + v[b,j]
// CTA tile 128x128, BK=16, double-buffered cp.async, 8 warps (2x4), warp 64x32
// A = raw c (HW tf32-truncates), B = rtf(q*w_cq)
// ---------------------------------------------------------------------------
__global__ __launch_bounds__(256,2) void gemm1_tc(const float* __restrict__ c)
{
    __shared__ float As[2][128][20];   // [stage][m][k]
    __shared__ float Bs[2][128][20];   // [stage][n][k]
    const int b  = blockIdx.z, m0 = blockIdx.y*128, n0 = blockIdx.x*128;
    const int tid = threadIdx.x;
    const int lane = tid & 31, wid = tid >> 5;
    const int wm = wid >> 2, wn = wid & 3;
    const int gid = lane >> 2, tig = lane & 3;
    const int cm = tid >> 2, ck = (tid & 3) * 4;

    const float* Ag = c    + ((size_t)b*CLEN + m0 + cm)*H + ck;
    const float* Bg = g_qs + ((size_t)b*QLEN + n0 + cm)*H + ck;
    const uint32_t sA = (uint32_t)__cvta_generic_to_shared(&As[0][cm][ck]);
    const uint32_t sB = (uint32_t)__cvta_generic_to_shared(&Bs[0][cm][ck]);

    float acc[4][4][4];
    #pragma unroll
    for (int i = 0; i < 4; i++)
        #pragma unroll
        for (int j = 0; j < 4; j++)
            #pragma unroll
            for (int r = 0; r < 4; r++) acc[i][j][r] = 0.f;

    CPA16(sA, Ag); CPA16(sA + 5120u, Ag + (size_t)64*H);
    CPA16(sB, Bg); CPA16(sB + 5120u, Bg + (size_t)64*H);
    CPCOMMIT();

    for (int i = 0; i < H/16; i++) {
        const int st = i & 1;
        if (i + 1 < H/16) {
            const int kc = (i+1)*16;
            const uint32_t oa = sA + (st^1)*10240u, ob = sB + (st^1)*10240u;
            CPA16(oa, Ag + kc); CPA16(oa + 5120u, Ag + (size_t)64*H + kc);
            CPA16(ob, Bg + kc); CPA16(ob + 5120u, Bg + (size_t)64*H + kc);
            CPCOMMIT();
            CPWAIT1();
        } else {
            CPWAIT0();
        }
        __syncthreads();
        #pragma unroll
        for (int kk = 0; kk < 16; kk += 8) {
            uint32_t a[4][4], bf[4][2];
            #pragma unroll
            for (int mt = 0; mt < 4; mt++) {
                int m = wm*64 + mt*16 + gid;
                a[mt][0] = __float_as_uint(As[st][m    ][kk+tig  ]);
                a[mt][1] = __float_as_uint(As[st][m + 8][kk+tig  ]);
                a[mt][2] = __float_as_uint(As[st][m    ][kk+tig+4]);
                a[mt][3] = __float_as_uint(As[st][m + 8][kk+tig+4]);
            }
            #pragma unroll
            for (int nt = 0; nt < 4; nt++) {
                int n = wn*32 + nt*8 + gid;
                bf[nt][0] = __float_as_uint(Bs[st][n][kk+tig  ]);
                bf[nt][1] = __float_as_uint(Bs[st][n][kk+tig+4]);
            }
            #pragma unroll
            for (int mt = 0; mt < 4; mt++)
                #pragma unroll
                for (int nt = 0; nt < 4; nt++)
                    mma_tf32(acc[mt][nt], a[mt], bf[nt]);
        }
        __syncthreads();
    }

    // epilogue: +v, write S
    const float* vb = g_v + b*QLEN + n0 + wn*32;
    float2 vv[4];
    #pragma unroll
    for (int nt = 0; nt < 4; nt++) vv[nt] = *(const float2*)&vb[nt*8 + 2*tig];
    #pragma unroll
    for (int mt = 0; mt < 4; mt++)
        #pragma unroll
        for (int r = 0; r < 2; r++) {
            int row = m0 + wm*64 + mt*16 + gid + 8*r;
            float* p = g_S + ((size_t)b*CLEN + row)*QLEN + n0 + wn*32;
            #pragma unroll
            for (int nt = 0; nt < 4; nt++) {
                float2 o = make_float2(acc[mt][nt][2*r]   + vv[nt].x,
                                       acc[mt][nt][2*r+1] + vv[nt].y);
                *(float2*)&p[nt*8 + 2*tig] = o;
            }
        }
}

// ---------------------------------------------------------------------------
// softmax over j (512): read S fp32, write probs fp16; g_m = rowmax + u
// warp per row, float2 / half2 vectorized
// ---------------------------------------------------------------------------
__global__ __launch_bounds__(256) void softmax_kernel()
{
    int warp = (blockIdx.x * blockDim.x + threadIdx.x) >> 5;
    if (warp >= B_ * CLEN) return;
    int lane = threadIdx.x & 31;
    const float2* row = (const float2*)(g_S + (size_t)warp * QLEN);
    __half2* ph = (__half2*)(g_P + (size_t)warp * QLEN);

    float2 v[8];
    float mx = -3.402823466e38f;
    #pragma unroll
    for (int t = 0; t < 8; t++) { v[t] = row[lane + t*32]; mx = fmaxf(mx, fmaxf(v[t].x, v[t].y)); }
    #pragma unroll
    for (int o = 16; o; o >>= 1) mx = fmaxf(mx, __shfl_xor_sync(0xffffffffu, mx, o));
    float s = 0.f;
    #pragma unroll
    for (int t = 0; t < 8; t++) {
        v[t].x = __expf(v[t].x - mx); v[t].y = __expf(v[t].y - mx);
        s += v[t].x + v[t].y;
    }
    #pragma unroll
    for (int o = 16; o; o >>= 1) s += __shfl_xor_sync(0xffffffffu, s, o);
    float inv = 1.f / s;
    #pragma unroll
    for (int t = 0; t < 8; t++)
        ph[lane + t*32] = __floats2half2_rn(v[t].x * inv, v[t].y * inv);
    if (lane == 0) g_m[warp] = mx + g_u[warp];
}

// ---------------------------------------------------------------------------
// q2c chain
// ---------------------------------------------------------------------------
__global__ __launch_bounds__(1024) void bmz_kernel()
{
    int b = blockIdx.x, tid = threadIdx.x;
    __shared__ float red[32];
    const float* m = g_m + b*CLEN;
    float mx = fmaxf(m[tid], fmaxf(m[tid+1024], fmaxf(m[tid+2048], m[tid+3072])));
    #pragma unroll
    for (int o = 16; o; o >>= 1) mx = fmaxf(mx, __shfl_xor_sync(0xffffffffu, mx, o));
    if ((tid & 31) == 0) red[tid >> 5] = mx;
    __syncthreads();
    mx = red[0];
    #pragma unroll
    for (int i = 1; i < 32; i++) mx = fmaxf(mx, red[i]);
    __syncthreads();
    float s = __expf(m[tid]-mx) + __expf(m[tid+1024]-mx)
            + __expf(m[tid+2048]-mx) + __expf(m[tid+3072]-mx);
    #pragma unroll
    for (int o = 16; o; o >>= 1) s += __shfl_xor_sync(0xffffffffu, s, o);
    if ((tid & 31) == 0) red[tid >> 5] = s;
    __syncthreads();
    if (tid == 0) {
        float Z = 0.f;
        #pragma unroll
        for (int i = 0; i < 32; i++) Z += red[i];
        g_bm[b] = mx; g_Z[b] = Z;
    }
}

__global__ __launch_bounds__(256) void q2c_part(const float* __restrict__ c)
{
    const int b = blockIdx.y, p = blockIdx.x, tid = threadIdx.x;
    __shared__ float w[128];
    if (tid < 128) w[tid] = __expf(g_m[b*CLEN + p*128 + tid] - g_bm[b]);
    __syncthreads();
    const float invZ = 1.f / g_Z[b];
    const float* cb = c + ((size_t)b*CLEN + p*128)*H + tid;
    float acc = 0.f;
    #pragma unroll 8
    for (int i = 0; i < 128; i++) acc = fmaf(w[i], cb[(size_t)i*H], acc);
    g_part[(b*32 + p)*H + tid] = acc * invZ;
}

__global__ __launch_bounds__(256) void q2c_reduce()
{
    int b = blockIdx.x, d = threadIdx.x;
    float s = 0.f;
    #pragma unroll
    for (int p = 0; p < 32; p++) s += g_part[(b*32 + p)*H + d];
    g_q2c[b*H + d] = s;
}

// ---------------------------------------------------------------------------
// GEMM2 (fp16 mma m16n8k16): c2q = P @ q, fused 4-section output epilogue
// CTA 128x128, K=512 in BK=32 chunks, A = probs fp16 [m][k], B = q^T fp16 [n][k]
// ---------------------------------------------------------------------------
__global__ __launch_bounds__(256,2) void gemm2_f16(
    const float* __restrict__ c, float* __restrict__ out)
{
    __shared__ __half As[2][128][40];   // [stage][m][k] pitch 40 halves = 80B
    __shared__ __half Bs[2][128][40];   // [stage][n][k]
    const int b  = blockIdx.z, m0 = blockIdx.y*128, n0 = blockIdx.x*128;
    const int tid = threadIdx.x;
    const int lane = tid & 31, wid = tid >> 5;
    const int wm = wid >> 2, wn = wid & 3;      // 2 x 4 warps; warp tile 64x32
    const int gid = lane >> 2, tig = lane & 3;
    const int cr = tid >> 1;                    // copy row 0..127
    const int cc = (tid & 1) * 16;              // half offset 0/16

    const __half* Ag = g_P  + ((size_t)b*CLEN + m0 + cr)*QLEN + cc;
    const __half* Bg = g_qt + ((size_t)b*H    + n0 + cr)*QLEN + cc;
    const uint32_t sA = (uint32_t)__cvta_generic_to_shared(&As[0][cr][cc]);
    const uint32_t sB = (uint32_t)__cvta_generic_to_shared(&Bs[0][cr][cc]);
    const uint32_t STG = 128u*40u*2u;   // 10240 bytes per stage

    float acc[4][4][4];
    #pragma unroll
    for (int i = 0; i < 4; i++)
        #pragma unroll
        for (int j = 0; j < 4; j++)
            #pragma unroll
            for (int r = 0; r < 4; r++) acc[i][j][r] = 0.f;

    // stage 0
    CPA16(sA, Ag); CPA16(sA + 16u, Ag + 8);
    CPA16(sB, Bg); CPA16(sB + 16u, Bg + 8);
    CPCOMMIT();

    for (int i = 0; i < QLEN/32; i++) {
        const int st = i & 1;
        if (i + 1 < QLEN/32) {
            const int kc = (i+1)*32;
            const uint32_t oa = sA + (st^1)*STG, ob = sB + (st^1)*STG;
            CPA16(oa, Ag + kc); CPA16(oa + 16u, Ag + kc + 8);
            CPA16(ob, Bg + kc); CPA16(ob + 16u, Bg + kc + 8);
            CPCOMMIT();
            CPWAIT1();
        } else {
            CPWAIT0();
        }
        __syncthreads();
        #pragma unroll
        for (int ks = 0; ks < 32; ks += 16) {
            uint32_t a[4][4], bf[4][2];
            #pragma unroll
            for (int mt = 0; mt < 4; mt++) {
                int m = wm*64 + mt*16 + gid;
                a[mt][0] = *(const uint32_t*)&As[st][m    ][ks + 2*tig    ];
                a[mt][1] = *(const uint32_t*)&As[st][m + 8][ks + 2*tig    ];
                a[mt][2] = *(const uint32_t*)&As[st][m    ][ks + 2*tig + 8];
                a[mt][3] = *(const uint32_t*)&As[st][m + 8][ks + 2*tig + 8];
            }
            #pragma unroll
            for (int nt = 0; nt < 4; nt++) {
                int n = wn*32 + nt*8 + gid;
                bf[nt][0] = *(const uint32_t*)&Bs[st][n][ks + 2*tig    ];
                bf[nt][1] = *(const uint32_t*)&Bs[st][n][ks + 2*tig + 8];
            }
            #pragma unroll
            for (int mt = 0; mt < 4; mt++)
                #pragma unroll
                for (int nt = 0; nt < 4; nt++)
                    mma_f16(acc[mt][nt], a[mt], bf[nt]);
        }
        __syncthreads();
    }

    // fused epilogue: out = [c | c2q | c*c2q | c*q2c]
    const int nbase = n0 + wn*32;
    float2 gv[4];
    #pragma unroll
    for (int nt = 0; nt < 4; nt++)
        gv[nt] = *(const float2*)&g_q2c[b*H + nbase + nt*8 + 2*tig];
    #pragma unroll
    for (int mt = 0; mt < 4; mt++)
        #pragma unroll
        for (int r = 0; r < 2; r++) {
            int row = m0 + wm*64 + mt*16 + gid + 8*r;
            const float* crow = c + ((size_t)b*CLEN + row)*H;
            float* orow = out + ((size_t)b*CLEN + row)*(4*H);
            #pragma unroll
            for (int nt = 0; nt < 4; nt++) {
                int col = nbase + nt*8 + 2*tig;
                float2 cv = *(const float2*)&crow[col];
                float2 av = make_float2(acc[mt][nt][2*r], acc[mt][nt][2*r+1]);
                *(float2*)&orow[col]       = cv;
                *(float2*)&orow[H + col]   = av;
                *(float2*)&orow[2*H + col] = make_float2(cv.x*av.x, cv.y*av.y);
                *(float2*)&orow[3*H + col] = make_float2(cv.x*gv[nt].x, cv.y*gv[nt].y);
            }
        }
}

// ---------------------------------------------------------------------------
extern "C" void kernel_launch(void* const* d_in, const int* in_sizes, int n_in,
                              void* d_out, int out_size)
{
    const float* c    = (const float*)d_in[0];
    const float* q    = (const float*)d_in[1];
    const float* w_c  = (const float*)d_in[2];
    const float* b_c  = (const float*)d_in[3];
    const float* w_q  = (const float*)d_in[4];
    const float* b_q  = (const float*)d_in[5];
    const float* w_cq = (const float*)d_in[6];
    const float* b_cq = (const float*)d_in[7];
    float* out = (float*)d_out;

    {   // q prep for gemm1
        size_t n4 = (size_t)B_*QLEN*(H/4);
        prep_q<<<(unsigned)((n4 + 255)/256), 256>>>((const float4*)q, (const float4*)w_cq);
    }
    {   // q^T fp16 for gemm2
        dim3 grid(QLEN/32, H/32, B_);
        qtrans_kernel<<<grid, dim3(32, 8)>>>(q);
    }
    {   // row dots
        int warps = B_*CLEN + B_*QLEN;
        uv_kernel<<<(warps*32 + 255)/256, 256>>>(c, q, w_c, b_c, w_q, b_q, b_cq);
    }
    {   // S = c.(q*w_cq)^T + v
        dim3 grid(QLEN/128, CLEN/128, B_);
        gemm1_tc<<<grid, 256>>>(c);
    }
    {   // row softmax -> fp16 probs
        int warps = B_*CLEN;
        softmax_kernel<<<(warps*32 + 255)/256, 256>>>();
    }
    bmz_kernel<<<B_, 1024>>>();
    {
        dim3 grid(32, B_);
        q2c_part<<<grid, 256>>>(c);
    }
    q2c_reduce<<<B_, 256>>>();
    {   // c2q + fused output
        dim3 grid(H/128, CLEN/128, B_);
        gemm2_f16<<<grid, 256>>>(c, out);
    }
}

// round 7
// speedup vs baseline: 1.6134x; 1.1217x over previous
#include <cuda_runtime.h>
#include <cuda_fp16.h>
#include <math.h>
#include <stdint.h>

#define B_   16
#define CLEN 4096
#define QLEN 512
#define H    256

// ---- scratch (device globals; allocation-free) ----
__device__ __align__(128) float  g_S [(size_t)B_*CLEN*QLEN];   // raw logits S (fp32)
__device__ __align__(128) __half g_P [(size_t)B_*CLEN*QLEN];   // probs fp16
__device__ __align__(128) __half g_ch[(size_t)B_*CLEN*H];      // c fp16
__device__ __align__(128) __half g_qsh[B_*QLEN*H];             // (q*w_cq) fp16
__device__ __align__(128) __half g_qt[B_*H*QLEN];              // q^T fp16 [b][d][j]
__device__ float g_u[B_*CLEN];
__device__ float g_v[B_*QLEN];
__device__ float g_m[B_*CLEN];
__device__ float g_bm[B_];
__device__ float g_Z[B_];
__device__ float g_part[B_*32*H];
__device__ float g_q2c[B_*H];

#define CPA16(s,g)  asm volatile("cp.async.cg.shared.global [%0], [%1], 16;\n" :: "r"(s), "l"(g))
#define CPCOMMIT()  asm volatile("cp.async.commit_group;\n")
#define CPWAIT0()   asm volatile("cp.async.wait_group 0;\n")
#define CPWAIT1()   asm volatile("cp.async.wait_group 1;\n")

__device__ __forceinline__ void mma_f16(float* d, const uint32_t* a, const uint32_t* b){
    asm volatile("mma.sync.aligned.m16n8k16.row.col.f32.f16.f16.f32 "
        "{%0,%1,%2,%3}, {%4,%5,%6,%7}, {%8,%9}, {%0,%1,%2,%3};"
        : "+f"(d[0]),"+f"(d[1]),"+f"(d[2]),"+f"(d[3])
        : "r"(a[0]),"r"(a[1]),"r"(a[2]),"r"(a[3]), "r"(b[0]),"r"(b[1]));
}

// ---------------------------------------------------------------------------
// prep: c -> fp16 g_ch ; (q*w_cq) -> fp16 g_qsh
// ---------------------------------------------------------------------------
__global__ __launch_bounds__(256) void prep_all(
    const float4* __restrict__ c, const float4* __restrict__ q,
    const float4* __restrict__ w)
{
    size_t i = (size_t)blockIdx.x * 256 + threadIdx.x;
    const size_t NC4 = (size_t)B_*CLEN*(H/4);
    const size_t NQ4 = (size_t)B_*QLEN*(H/4);
    if (i < NC4) {
        float4 x = c[i];
        union { __half2 h2[2]; uint2 u; } t;
        t.h2[0] = __floats2half2_rn(x.x, x.y);
        t.h2[1] = __floats2half2_rn(x.z, x.w);
        ((uint2*)g_ch)[i] = t.u;
    } else if (i < NC4 + NQ4) {
        size_t j = i - NC4;
        float4 x = q[j];
        float4 wv = w[j & (H/4 - 1)];
        union { __half2 h2[2]; uint2 u; } t;
        t.h2[0] = __floats2half2_rn(x.x*wv.x, x.y*wv.y);
        t.h2[1] = __floats2half2_rn(x.z*wv.z, x.w*wv.w);
        ((uint2*)g_qsh)[j] = t.u;
    }
}

// ---------------------------------------------------------------------------
// qtrans: q[b][j][d] fp32 -> g_qt[b][d][j] fp16
// ---------------------------------------------------------------------------
__global__ void qtrans_kernel(const float* __restrict__ q)
{
    __shared__ float tile[32][33];
    const int j0 = blockIdx.x * 32, d0 = blockIdx.y * 32, b = blockIdx.z;
    const int tx = threadIdx.x, ty = threadIdx.y;   // 32 x 8
    #pragma unroll
    for (int r = 0; r < 4; r++)
        tile[ty + 8*r][tx] = q[((size_t)b*QLEN + j0 + ty + 8*r)*H + d0 + tx];
    __syncthreads();
    #pragma unroll
    for (int r = 0; r < 4; r++) {
        int d = d0 + ty + 8*r, j = j0 + tx;
        g_qt[((size_t)b*H + d)*QLEN + j] = __float2half_rn(tile[tx][ty + 8*r]);
    }
}

// ---------------------------------------------------------------------------
// uv: u[b,i] = c_i.w_c + b_c ; v[b,j] = q_j.w_q + b_q + b_cq   (warp/row)
// ---------------------------------------------------------------------------
__global__ __launch_bounds__(256) void uv_kernel(
    const float* __restrict__ c, const float* __restrict__ q,
    const float* __restrict__ w_c, const float* __restrict__ b_c,
    const float* __restrict__ w_q, const float* __restrict__ b_q,
    const float* __restrict__ b_cq)
{
    int warp = (blockIdx.x * blockDim.x + threadIdx.x) >> 5;
    int lane = threadIdx.x & 31;
    if (warp < B_ * CLEN) {
        const float* row = c + (size_t)warp * H;
        float s = 0.f;
        #pragma unroll
        for (int t = 0; t < H/32; t++) s = fmaf(row[lane + t*32], w_c[lane + t*32], s);
        #pragma unroll
        for (int o = 16; o; o >>= 1) s += __shfl_xor_sync(0xffffffffu, s, o);
        if (lane == 0) g_u[warp] = s + b_c[0];
    } else {
        int r = warp - B_ * CLEN;
        if (r < B_ * QLEN) {
            const float* row = q + (size_t)r * H;
            float s = 0.f;
            #pragma unroll
            for (int t = 0; t < H/32; t++) s = fmaf(row[lane + t*32], w_q[lane + t*32], s);
            #pragma unroll
            for (int o = 16; o; o >>= 1) s += __shfl_xor_sync(0xffffffffu, s, o);
            if (lane == 0) g_v[r] = s + b_q[0] + b_cq[0];
        }
    }
}

// ---------------------------------------------------------------------------
// GEMM1 (fp16 mma m16n8k16): S[b,i,j] = sum_d ch[b,i,d]*qsh[b,j,d] + v[b,j]
// CTA 128x128, K=256 in BK=32 chunks, A=[m][k], B=[n][k], 8 warps (2x4)
// ---------------------------------------------------------------------------
__global__ __launch_bounds__(256,2) void gemm1_f16()
{
    __shared__ __half As[2][128][40];   // [stage][m][k] pitch 40 halves
    __shared__ __half Bs[2][128][40];   // [stage][n][k]
    const int b  = blockIdx.z, m0 = blockIdx.y*128, n0 = blockIdx.x*128;
    const int tid = threadIdx.x;
    const int lane = tid & 31, wid = tid >> 5;
    const int wm = wid >> 2, wn = wid & 3;
    const int gid = lane >> 2, tig = lane & 3;
    const int cr = tid >> 1;            // copy row 0..127
    const int cc = (tid & 1) * 16;      // half offset 0/16

    const __half* Ag = g_ch  + ((size_t)b*CLEN + m0 + cr)*H + cc;
    const __half* Bg = g_qsh + ((size_t)b*QLEN + n0 + cr)*H + cc;
    const uint32_t sA = (uint32_t)__cvta_generic_to_shared(&As[0][cr][cc]);
    const uint32_t sB = (uint32_t)__cvta_generic_to_shared(&Bs[0][cr][cc]);
    const uint32_t STG = 128u*40u*2u;   // 10240 B per stage

    float acc[4][4][4];
    #pragma unroll
    for (int i = 0; i < 4; i++)
        #pragma unroll
        for (int j = 0; j < 4; j++)
            #pragma unroll
            for (int r = 0; r < 4; r++) acc[i][j][r] = 0.f;

    CPA16(sA, Ag); CPA16(sA + 16u, Ag + 8);
    CPA16(sB, Bg); CPA16(sB + 16u, Bg + 8);
    CPCOMMIT();

    for (int i = 0; i < H/32; i++) {
        const int st = i & 1;
        if (i + 1 < H/32) {
            const int kc = (i+1)*32;
            const uint32_t oa = sA + (st^1)*STG, ob = sB + (st^1)*STG;
            CPA16(oa, Ag + kc); CPA16(oa + 16u, Ag + kc + 8);
            CPA16(ob, Bg + kc); CPA16(ob + 16u, Bg + kc + 8);
            CPCOMMIT();
            CPWAIT1();
        } else {
            CPWAIT0();
        }
        __syncthreads();
        #pragma unroll
        for (int ks = 0; ks < 32; ks += 16) {
            uint32_t a[4][4], bf[4][2];
            #pragma unroll
            for (int mt = 0; mt < 4; mt++) {
                int m = wm*64 + mt*16 + gid;
                a[mt][0] = *(const uint32_t*)&As[st][m    ][ks + 2*tig    ];
                a[mt][1] = *(const uint32_t*)&As[st][m + 8][ks + 2*tig    ];
                a[mt][2] = *(const uint32_t*)&As[st][m    ][ks + 2*tig + 8];
                a[mt][3] = *(const uint32_t*)&As[st][m + 8][ks + 2*tig + 8];
            }
            #pragma unroll
            for (int nt = 0; nt < 4; nt++) {
                int n = wn*32 + nt*8 + gid;
                bf[nt][0] = *(const uint32_t*)&Bs[st][n][ks + 2*tig    ];
                bf[nt][1] = *(const uint32_t*)&Bs[st][n][ks + 2*tig + 8];
            }
            #pragma unroll
            for (int mt = 0; mt < 4; mt++)
                #pragma unroll
                for (int nt = 0; nt < 4; nt++)
                    mma_f16(acc[mt][nt], a[mt], bf[nt]);
        }
        __syncthreads();
    }

    // epilogue: +v, write S fp32
    const float* vb = g_v + b*QLEN + n0 + wn*32;
    float2 vv[4];
    #pragma unroll
    for (int nt = 0; nt < 4; nt++) vv[nt] = *(const float2*)&vb[nt*8 + 2*tig];
    #pragma unroll
    for (int mt = 0; mt < 4; mt++)
        #pragma unroll
        for (int r = 0; r < 2; r++) {
            int row = m0 + wm*64 + mt*16 + gid + 8*r;
            float* p = g_S + ((size_t)b*CLEN + row)*QLEN + n0 + wn*32;
            #pragma unroll
            for (int nt = 0; nt < 4; nt++) {
                float2 o = make_float2(acc[mt][nt][2*r]   + vv[nt].x,
                                       acc[mt][nt][2*r+1] + vv[nt].y);
                *(float2*)&p[nt*8 + 2*tig] = o;
            }
        }
}

// ---------------------------------------------------------------------------
// softmax over j (512): read S fp32, write probs fp16; g_m = rowmax + u
// ---------------------------------------------------------------------------
__global__ __launch_bounds__(256) void softmax_kernel()
{
    int warp = (blockIdx.x * blockDim.x + threadIdx.x) >> 5;
    if (warp >= B_ * CLEN) return;
    int lane = threadIdx.x & 31;
    const float2* row = (const float2*)(g_S + (size_t)warp * QLEN);
    __half2* ph = (__half2*)(g_P + (size_t)warp * QLEN);

    float2 v[8];
    float mx = -3.402823466e38f;
    #pragma unroll
    for (int t = 0; t < 8; t++) { v[t] = row[lane + t*32]; mx = fmaxf(mx, fmaxf(v[t].x, v[t].y)); }
    #pragma unroll
    for (int o = 16; o; o >>= 1) mx = fmaxf(mx, __shfl_xor_sync(0xffffffffu, mx, o));
    float s = 0.f;
    #pragma unroll
    for (int t = 0; t < 8; t++) {
        v[t].x = __expf(v[t].x - mx); v[t].y = __expf(v[t].y - mx);
        s += v[t].x + v[t].y;
    }
    #pragma unroll
    for (int o = 16; o; o >>= 1) s += __shfl_xor_sync(0xffffffffu, s, o);
    float inv = 1.f / s;
    #pragma unroll
    for (int t = 0; t < 8; t++)
        ph[lane + t*32] = __floats2half2_rn(v[t].x * inv, v[t].y * inv);
    if (lane == 0) g_m[warp] = mx + g_u[warp];
}

// ---------------------------------------------------------------------------
// q2c chain
// ---------------------------------------------------------------------------
__global__ __launch_bounds__(1024) void bmz_kernel()
{
    int b = blockIdx.x, tid = threadIdx.x;
    __shared__ float red[32];
    const float* m = g_m + b*CLEN;
    float mx = fmaxf(m[tid], fmaxf(m[tid+1024], fmaxf(m[tid+2048], m[tid+3072])));
    #pragma unroll
    for (int o = 16; o; o >>= 1) mx = fmaxf(mx, __shfl_xor_sync(0xffffffffu, mx, o));
    if ((tid & 31) == 0) red[tid >> 5] = mx;
    __syncthreads();
    mx = red[0];
    #pragma unroll
    for (int i = 1; i < 32; i++) mx = fmaxf(mx, red[i]);
    __syncthreads();
    float s = __expf(m[tid]-mx) + __expf(m[tid+1024]-mx)
            + __expf(m[tid+2048]-mx) + __expf(m[tid+3072]-mx);
    #pragma unroll
    for (int o = 16; o; o >>= 1) s += __shfl_xor_sync(0xffffffffu, s, o);
    if ((tid & 31) == 0) red[tid >> 5] = s;
    __syncthreads();
    if (tid == 0) {
        float Z = 0.f;
        #pragma unroll
        for (int i = 0; i < 32; i++) Z += red[i];
        g_bm[b] = mx; g_Z[b] = Z;
    }
}

__global__ __launch_bounds__(256) void q2c_part(const float* __restrict__ c)
{
    const int b = blockIdx.y, p = blockIdx.x, tid = threadIdx.x;
    __shared__ float w[128];
    if (tid < 128) w[tid] = __expf(g_m[b*CLEN + p*128 + tid] - g_bm[b]);
    __syncthreads();
    const float invZ = 1.f / g_Z[b];
    const float* cb = c + ((size_t)b*CLEN + p*128)*H + tid;
    float acc = 0.f;
    #pragma unroll 8
    for (int i = 0; i < 128; i++) acc = fmaf(w[i], cb[(size_t)i*H], acc);
    g_part[(b*32 + p)*H + tid] = acc * invZ;
}

__global__ __launch_bounds__(256) void q2c_reduce()
{
    int b = blockIdx.x, d = threadIdx.x;
    float s = 0.f;
    #pragma unroll
    for (int p = 0; p < 32; p++) s += g_part[(b*32 + p)*H + d];
    g_q2c[b*H + d] = s;
}

// ---------------------------------------------------------------------------
// GEMM2 (fp16 mma m16n8k16): c2q = P @ q, fused 4-section output epilogue
// ---------------------------------------------------------------------------
__global__ __launch_bounds__(256,2) void gemm2_f16(
    const float* __restrict__ c, float* __restrict__ out)
{
    __shared__ __half As[2][128][40];
    __shared__ __half Bs[2][128][40];
    const int b  = blockIdx.z, m0 = blockIdx.y*128, n0 = blockIdx.x*128;
    const int tid = threadIdx.x;
    const int lane = tid & 31, wid = tid >> 5;
    const int wm = wid >> 2, wn = wid & 3;
    const int gid = lane >> 2, tig = lane & 3;
    const int cr = tid >> 1;
    const int cc = (tid & 1) * 16;

    const __half* Ag = g_P  + ((size_t)b*CLEN + m0 + cr)*QLEN + cc;
    const __half* Bg = g_qt + ((size_t)b*H    + n0 + cr)*QLEN + cc;
    const uint32_t sA = (uint32_t)__cvta_generic_to_shared(&As[0][cr][cc]);
    const uint32_t sB = (uint32_t)__cvta_generic_to_shared(&Bs[0][cr][cc]);
    const uint32_t STG = 128u*40u*2u;

    float acc[4][4][4];
    #pragma unroll
    for (int i = 0; i < 4; i++)
        #pragma unroll
        for (int j = 0; j < 4; j++)
            #pragma unroll
            for (int r = 0; r < 4; r++) acc[i][j][r] = 0.f;

    CPA16(sA, Ag); CPA16(sA + 16u, Ag + 8);
    CPA16(sB, Bg); CPA16(sB + 16u, Bg + 8);
    CPCOMMIT();

    for (int i = 0; i < QLEN/32; i++) {
        const int st = i & 1;
        if (i + 1 < QLEN/32) {
            const int kc = (i+1)*32;
            const uint32_t oa = sA + (st^1)*STG, ob = sB + (st^1)*STG;
            CPA16(oa, Ag + kc); CPA16(oa + 16u, Ag + kc + 8);
            CPA16(ob, Bg + kc); CPA16(ob + 16u, Bg + kc + 8);
            CPCOMMIT();
            CPWAIT1();
        } else {
            CPWAIT0();
        }
        __syncthreads();
        #pragma unroll
        for (int ks = 0; ks < 32; ks += 16) {
            uint32_t a[4][4], bf[4][2];
            #pragma unroll
            for (int mt = 0; mt < 4; mt++) {
                int m = wm*64 + mt*16 + gid;
                a[mt][0] = *(const uint32_t*)&As[st][m    ][ks + 2*tig    ];
                a[mt][1] = *(const uint32_t*)&As[st][m + 8][ks + 2*tig    ];
                a[mt][2] = *(const uint32_t*)&As[st][m    ][ks + 2*tig + 8];
                a[mt][3] = *(const uint32_t*)&As[st][m + 8][ks + 2*tig + 8];
            }
            #pragma unroll
            for (int nt = 0; nt < 4; nt++) {
                int n = wn*32 + nt*8 + gid;
                bf[nt][0] = *(const uint32_t*)&Bs[st][n][ks + 2*tig    ];
                bf[nt][1] = *(const uint32_t*)&Bs[st][n][ks + 2*tig + 8];
            }
            #pragma unroll
            for (int mt = 0; mt < 4; mt++)
                #pragma unroll
                for (int nt = 0; nt < 4; nt++)
                    mma_f16(acc[mt][nt], a[mt], bf[nt]);
        }
        __syncthreads();
    }

    // fused epilogue: out = [c | c2q | c*c2q | c*q2c]
    const int nbase = n0 + wn*32;
    float2 gv[4];
    #pragma unroll
    for (int nt = 0; nt < 4; nt++)
        gv[nt] = *(const float2*)&g_q2c[b*H + nbase + nt*8 + 2*tig];
    #pragma unroll
    for (int mt = 0; mt < 4; mt++)
        #pragma unroll
        for (int r = 0; r < 2; r++) {
            int row = m0 + wm*64 + mt*16 + gid + 8*r;
            const float* crow = c + ((size_t)b*CLEN + row)*H;
            float* orow = out + ((size_t)b*CLEN + row)*(4*H);
            #pragma unroll
            for (int nt = 0; nt < 4; nt++) {
                int col = nbase + nt*8 + 2*tig;
                float2 cv = *(const float2*)&crow[col];
                float2 av = make_float2(acc[mt][nt][2*r], acc[mt][nt][2*r+1]);
                *(float2*)&orow[col]       = cv;
                *(float2*)&orow[H + col]   = av;
                *(float2*)&orow[2*H + col] = make_float2(cv.x*av.x, cv.y*av.y);
                *(float2*)&orow[3*H + col] = make_float2(cv.x*gv[nt].x, cv.y*gv[nt].y);
            }
        }
}

// ---------------------------------------------------------------------------
extern "C" void kernel_launch(void* const* d_in, const int* in_sizes, int n_in,
                              void* d_out, int out_size)
{
    const float* c    = (const float*)d_in[0];
    const float* q    = (const float*)d_in[1];
    const float* w_c  = (const float*)d_in[2];
    const float* b_c  = (const float*)d_in[3];
    const float* w_q  = (const float*)d_in[4];
    const float* b_q  = (const float*)d_in[5];
    const float* w_cq = (const float*)d_in[6];
    const float* b_cq = (const float*)d_in[7];
    float* out = (float*)d_out;

    {   // fp16 conversions
        size_t n4 = (size_t)B_*CLEN*(H/4) + (size_t)B_*QLEN*(H/4);
        prep_all<<<(unsigned)((n4 + 255)/256), 256>>>(
            (const float4*)c, (const float4*)q, (const float4*)w_cq);
    }
    {   // q^T fp16 for gemm2
        dim3 grid(QLEN/32, H/32, B_);
        qtrans_kernel<<<grid, dim3(32, 8)>>>(q);
    }
    {   // row dots
        int warps = B_*CLEN + B_*QLEN;
        uv_kernel<<<(warps*32 + 255)/256, 256>>>(c, q, w_c, b_c, w_q, b_q, b_cq);
    }
    {   // S = c.(q*w_cq)^T + v   (fp16 tensor cores)
        dim3 grid(QLEN/128, CLEN/128, B_);
        gemm1_f16<<<grid, 256>>>();
    }
    {   // row softmax -> fp16 probs
        int warps = B_*CLEN;
        softmax_kernel<<<(warps*32 + 255)/256, 256>>>();
    }
    bmz_kernel<<<B_, 1024>>>();
    {
        dim3 grid(32, B_);
        q2c_part<<<grid, 256>>>(c);
    }
    q2c_reduce<<<B_, 256>>>();
    {   // c2q + fused output
        dim3 grid(H/128, CLEN/128, B_);
        gemm2_f16<<<grid, 256>>>(c, out);
    }
}

// round 8
// speedup vs baseline: 1.7794x; 1.1029x over previous
#include <cuda_runtime.h>
#include <cuda_fp16.h>
#include <math.h>
#include <stdint.h>

#define B_   16
#define CLEN 4096
#define QLEN 512
#define H    256

// ---- scratch (device globals; allocation-free) ----
__device__ __align__(128) float  g_S [(size_t)B_*CLEN*QLEN];   // raw logits S (fp32)
__device__ __align__(128) __half g_P [(size_t)B_*CLEN*QLEN];   // probs fp16
__device__ __align__(128) __half g_ch[(size_t)B_*CLEN*H];      // c fp16
__device__ __align__(128) __half g_qsh[B_*QLEN*H];             // (q*w_cq) fp16
__device__ __align__(128) __half g_qt[B_*H*QLEN];              // q^T fp16 [b][d][j]
__device__ float g_u[B_*CLEN];
__device__ float g_v[B_*QLEN];
__device__ float g_m[B_*CLEN];
__device__ float g_bm[B_];
__device__ float g_Z[B_];
__device__ float g_part[B_*32*H];
__device__ float g_q2c[B_*H];

#define CPA16(s,g)  asm volatile("cp.async.cg.shared.global [%0], [%1], 16;\n" :: "r"(s), "l"(g))
#define CPCOMMIT()  asm volatile("cp.async.commit_group;\n")
#define CPWAIT0()   asm volatile("cp.async.wait_group 0;\n")
#define CPWAIT1()   asm volatile("cp.async.wait_group 1;\n")

#define LDSM4(r0,r1,r2,r3,addr) \
    asm volatile("ldmatrix.sync.aligned.m8n8.x4.shared.b16 {%0,%1,%2,%3}, [%4];" \
        : "=r"(r0),"=r"(r1),"=r"(r2),"=r"(r3) : "r"(addr))

__device__ __forceinline__ void mma_f16(float* d, const uint32_t* a, const uint32_t* b){
    asm volatile("mma.sync.aligned.m16n8k16.row.col.f32.f16.f16.f32 "
        "{%0,%1,%2,%3}, {%4,%5,%6,%7}, {%8,%9}, {%0,%1,%2,%3};"
        : "+f"(d[0]),"+f"(d[1]),"+f"(d[2]),"+f"(d[3])
        : "r"(a[0]),"r"(a[1]),"r"(a[2]),"r"(a[3]), "r"(b[0]),"r"(b[1]));
}

// tile geometry shared by both GEMMs: CTA 128x128, BK=32, pitch 40 halves
#define PITCH   40
#define TILEB   10240u            // 128*40*2 bytes per operand per stage
#define BOFF    30720u            // B tiles start after 3 A stages
#define SMEMSZ  61440             // 2 * 3 * TILEB

// ---------------------------------------------------------------------------
// prep: c -> fp16 g_ch ; (q*w_cq) -> fp16 g_qsh
// ---------------------------------------------------------------------------
__global__ __launch_bounds__(256) void prep_all(
    const float4* __restrict__ c, const float4* __restrict__ q,
    const float4* __restrict__ w)
{
    size_t i = (size_t)blockIdx.x * 256 + threadIdx.x;
    const size_t NC4 = (size_t)B_*CLEN*(H/4);
    const size_t NQ4 = (size_t)B_*QLEN*(H/4);
    if (i < NC4) {
        float4 x = c[i];
        union { __half2 h2[2]; uint2 u; } t;
        t.h2[0] = __floats2half2_rn(x.x, x.y);
        t.h2[1] = __floats2half2_rn(x.z, x.w);
        ((uint2*)g_ch)[i] = t.u;
    } else if (i < NC4 + NQ4) {
        size_t j = i - NC4;
        float4 x = q[j];
        float4 wv = w[j & (H/4 - 1)];
        union { __half2 h2[2]; uint2 u; } t;
        t.h2[0] = __floats2half2_rn(x.x*wv.x, x.y*wv.y);
        t.h2[1] = __floats2half2_rn(x.z*wv.z, x.w*wv.w);
        ((uint2*)g_qsh)[j] = t.u;
    }
}

// ---------------------------------------------------------------------------
// qtrans: q[b][j][d] fp32 -> g_qt[b][d][j] fp16
// ---------------------------------------------------------------------------
__global__ void qtrans_kernel(const float* __restrict__ q)
{
    __shared__ float tile[32][33];
    const int j0 = blockIdx.x * 32, d0 = blockIdx.y * 32, b = blockIdx.z;
    const int tx = threadIdx.x, ty = threadIdx.y;   // 32 x 8
    #pragma unroll
    for (int r = 0; r < 4; r++)
        tile[ty + 8*r][tx] = q[((size_t)b*QLEN + j0 + ty + 8*r)*H + d0 + tx];
    __syncthreads();
    #pragma unroll
    for (int r = 0; r < 4; r++) {
        int d = d0 + ty + 8*r, j = j0 + tx;
        g_qt[((size_t)b*H + d)*QLEN + j] = __float2half_rn(tile[tx][ty + 8*r]);
    }
}

// ---------------------------------------------------------------------------
// uv: u[b,i] = c_i.w_c + b_c ; v[b,j] = q_j.w_q + b_q + b_cq   (warp/row)
// ---------------------------------------------------------------------------
__global__ __launch_bounds__(256) void uv_kernel(
    const float* __restrict__ c, const float* __restrict__ q,
    const float* __restrict__ w_c, const float* __restrict__ b_c,
    const float* __restrict__ w_q, const float* __restrict__ b_q,
    const float* __restrict__ b_cq)
{
    int warp = (blockIdx.x * blockDim.x + threadIdx.x) >> 5;
    int lane = threadIdx.x & 31;
    if (warp < B_ * CLEN) {
        const float* row = c + (size_t)warp * H;
        float s = 0.f;
        #pragma unroll
        for (int t = 0; t < H/32; t++) s = fmaf(row[lane + t*32], w_c[lane + t*32], s);
        #pragma unroll
        for (int o = 16; o; o >>= 1) s += __shfl_xor_sync(0xffffffffu, s, o);
        if (lane == 0) g_u[warp] = s + b_c[0];
    } else {
        int r = warp - B_ * CLEN;
        if (r < B_ * QLEN) {
            const float* row = q + (size_t)r * H;
            float s = 0.f;
            #pragma unroll
            for (int t = 0; t < H/32; t++) s = fmaf(row[lane + t*32], w_q[lane + t*32], s);
            #pragma unroll
            for (int o = 16; o; o >>= 1) s += __shfl_xor_sync(0xffffffffu, s, o);
            if (lane == 0) g_v[r] = s + b_q[0] + b_cq[0];
        }
    }
}

// ---------------------------------------------------------------------------
// GEMM1 (fp16 mma + ldmatrix + 3-stage): S = c.(q*w_cq)^T + v
// ---------------------------------------------------------------------------
__global__ __launch_bounds__(256,2) void gemm1_f16()
{
    extern __shared__ __align__(128) char dsm[];
    const int b  = blockIdx.z, m0 = blockIdx.y*128, n0 = blockIdx.x*128;
    const int tid = threadIdx.x;
    const int lane = tid & 31, wid = tid >> 5;
    const int wm = wid >> 2, wn = wid & 3;
    const int gid = lane >> 2, tig = lane & 3;
    const int cr = tid >> 1;            // copy row 0..127
    const int cc = (tid & 1) * 16;      // half offset 0/16

    const __half* Ag = g_ch  + ((size_t)b*CLEN + m0 + cr)*H + cc;
    const __half* Bg = g_qsh + ((size_t)b*QLEN + n0 + cr)*H + cc;
    const uint32_t sbase = (uint32_t)__cvta_generic_to_shared(dsm);
    const uint32_t wOff = (uint32_t)(cr*PITCH + cc)*2u;

    // ldmatrix per-lane offsets (bytes)
    const int rA = lane & 15, cA = (lane & 16) >> 1;            // rows m.., col +0/8
    const int rB = (lane & 7) + ((lane & 16) >> 1), cB = lane & 8;
    const uint32_t offA = (uint32_t)(rA*PITCH + cA)*2u;
    const uint32_t offB = (uint32_t)(rB*PITCH + cB)*2u;

    float acc[4][4][4];
    #pragma unroll
    for (int i = 0; i < 4; i++)
        #pragma unroll
        for (int j = 0; j < 4; j++)
            #pragma unroll
            for (int r = 0; r < 4; r++) acc[i][j][r] = 0.f;

    const int NIT = H/32;   // 8
    // prologue: stages 0,1
    #pragma unroll
    for (int p = 0; p < 2; p++) {
        const uint32_t sa = sbase + p*TILEB + wOff;
        const uint32_t sb = sbase + BOFF + p*TILEB + wOff;
        CPA16(sa, Ag + p*32); CPA16(sa + 16u, Ag + p*32 + 8);
        CPA16(sb, Bg + p*32); CPA16(sb + 16u, Bg + p*32 + 8);
        CPCOMMIT();
    }

    for (int i = 0; i < NIT; i++) {
        if (i == NIT-1) { CPWAIT0(); } else { CPWAIT1(); }
        __syncthreads();
        const int st = i % 3;
        const uint32_t aBase = sbase + st*TILEB + (uint32_t)(wm*64)*PITCH*2u + offA;
        const uint32_t bBase = sbase + BOFF + st*TILEB + (uint32_t)(wn*32)*PITCH*2u + offB;
        #pragma unroll
        for (int ks = 0; ks < 32; ks += 16) {
            uint32_t a[4][4], bf[4][2];
            #pragma unroll
            for (int mt = 0; mt < 4; mt++)
                LDSM4(a[mt][0], a[mt][1], a[mt][2], a[mt][3],
                      aBase + (uint32_t)(mt*16)*PITCH*2u + ks*2u);
            #pragma unroll
            for (int p = 0; p < 2; p++)
                LDSM4(bf[2*p][0], bf[2*p][1], bf[2*p+1][0], bf[2*p+1][1],
                      bBase + (uint32_t)(p*16)*PITCH*2u + ks*2u);
            #pragma unroll
            for (int mt = 0; mt < 4; mt++)
                #pragma unroll
                for (int nt = 0; nt < 4; nt++)
                    mma_f16(acc[mt][nt], a[mt], bf[nt]);
        }
        if (i + 2 < NIT) {
            const int kc = (i+2)*32, s2 = (i+2) % 3;
            const uint32_t sa = sbase + s2*TILEB + wOff;
            const uint32_t sb = sbase + BOFF + s2*TILEB + wOff;
            CPA16(sa, Ag + kc); CPA16(sa + 16u, Ag + kc + 8);
            CPA16(sb, Bg + kc); CPA16(sb + 16u, Bg + kc + 8);
            CPCOMMIT();
        }
    }

    // epilogue: +v, write S fp32
    const float* vb = g_v + b*QLEN + n0 + wn*32;
    float2 vv[4];
    #pragma unroll
    for (int nt = 0; nt < 4; nt++) vv[nt] = *(const float2*)&vb[nt*8 + 2*tig];
    #pragma unroll
    for (int mt = 0; mt < 4; mt++)
        #pragma unroll
        for (int r = 0; r < 2; r++) {
            int row = m0 + wm*64 + mt*16 + gid + 8*r;
            float* p = g_S + ((size_t)b*CLEN + row)*QLEN + n0 + wn*32;
            #pragma unroll
            for (int nt = 0; nt < 4; nt++) {
                float2 o = make_float2(acc[mt][nt][2*r]   + vv[nt].x,
                                       acc[mt][nt][2*r+1] + vv[nt].y);
                *(float2*)&p[nt*8 + 2*tig] = o;
            }
        }
}

// ---------------------------------------------------------------------------
// softmax over j (512): read S fp32, write probs fp16; g_m = rowmax + u
// ---------------------------------------------------------------------------
__global__ __launch_bounds__(256) void softmax_kernel()
{
    int warp = (blockIdx.x * blockDim.x + threadIdx.x) >> 5;
    if (warp >= B_ * CLEN) return;
    int lane = threadIdx.x & 31;
    const float2* row = (const float2*)(g_S + (size_t)warp * QLEN);
    __half2* ph = (__half2*)(g_P + (size_t)warp * QLEN);

    float2 v[8];
    float mx = -3.402823466e38f;
    #pragma unroll
    for (int t = 0; t < 8; t++) { v[t] = row[lane + t*32]; mx = fmaxf(mx, fmaxf(v[t].x, v[t].y)); }
    #pragma unroll
    for (int o = 16; o; o >>= 1) mx = fmaxf(mx, __shfl_xor_sync(0xffffffffu, mx, o));
    float s = 0.f;
    #pragma unroll
    for (int t = 0; t < 8; t++) {
        v[t].x = __expf(v[t].x - mx); v[t].y = __expf(v[t].y - mx);
        s += v[t].x + v[t].y;
    }
    #pragma unroll
    for (int o = 16; o; o >>= 1) s += __shfl_xor_sync(0xffffffffu, s, o);
    float inv = 1.f / s;
    #pragma unroll
    for (int t = 0; t < 8; t++)
        ph[lane + t*32] = __floats2half2_rn(v[t].x * inv, v[t].y * inv);
    if (lane == 0) g_m[warp] = mx + g_u[warp];
}

// ---------------------------------------------------------------------------
// q2c chain
// ---------------------------------------------------------------------------
__global__ __launch_bounds__(1024) void bmz_kernel()
{
    int b = blockIdx.x, tid = threadIdx.x;
    __shared__ float red[32];
    const float* m = g_m + b*CLEN;
    float mx = fmaxf(m[tid], fmaxf(m[tid+1024], fmaxf(m[tid+2048], m[tid+3072])));
    #pragma unroll
    for (int o = 16; o; o >>= 1) mx = fmaxf(mx, __shfl_xor_sync(0xffffffffu, mx, o));
    if ((tid & 31) == 0) red[tid >> 5] = mx;
    __syncthreads();
    mx = red[0];
    #pragma unroll
    for (int i = 1; i < 32; i++) mx = fmaxf(mx, red[i]);
    __syncthreads();
    float s = __expf(m[tid]-mx) + __expf(m[tid+1024]-mx)
            + __expf(m[tid+2048]-mx) + __expf(m[tid+3072]-mx);
    #pragma unroll
    for (int o = 16; o; o >>= 1) s += __shfl_xor_sync(0xffffffffu, s, o);
    if ((tid & 31) == 0) red[tid >> 5] = s;
    __syncthreads();
    if (tid == 0) {
        float Z = 0.f;
        #pragma unroll
        for (int i = 0; i < 32; i++) Z += red[i];
        g_bm[b] = mx; g_Z[b] = Z;
    }
}

__global__ __launch_bounds__(256) void q2c_part(const float* __restrict__ c)
{
    const int b = blockIdx.y, p = blockIdx.x, tid = threadIdx.x;
    __shared__ float w[128];
    if (tid < 128) w[tid] = __expf(g_m[b*CLEN + p*128 + tid] - g_bm[b]);
    __syncthreads();
    const float invZ = 1.f / g_Z[b];
    const float* cb = c + ((size_t)b*CLEN + p*128)*H + tid;
    float acc = 0.f;
    #pragma unroll 8
    for (int i = 0; i < 128; i++) acc = fmaf(w[i], cb[(size_t)i*H], acc);
    g_part[(b*32 + p)*H + tid] = acc * invZ;
}

__global__ __launch_bounds__(256) void q2c_reduce()
{
    int b = blockIdx.x, d = threadIdx.x;
    float s = 0.f;
    #pragma unroll
    for (int p = 0; p < 32; p++) s += g_part[(b*32 + p)*H + d];
    g_q2c[b*H + d] = s;
}

// ---------------------------------------------------------------------------
// GEMM2 (fp16 mma + ldmatrix + 3-stage): c2q = P @ q, fused 4-section epilogue
// ---------------------------------------------------------------------------
__global__ __launch_bounds__(256,2) void gemm2_f16(
    const float* __restrict__ c, float* __restrict__ out)
{
    extern __shared__ __align__(128) char dsm[];
    const int b  = blockIdx.z, m0 = blockIdx.y*128, n0 = blockIdx.x*128;
    const int tid = threadIdx.x;
    const int lane = tid & 31, wid = tid >> 5;
    const int wm = wid >> 2, wn = wid & 3;
    const int gid = lane >> 2, tig = lane & 3;
    const int cr = tid >> 1;
    const int cc = (tid & 1) * 16;

    const __half* Ag = g_P  + ((size_t)b*CLEN + m0 + cr)*QLEN + cc;
    const __half* Bg = g_qt + ((size_t)b*H    + n0 + cr)*QLEN + cc;
    const uint32_t sbase = (uint32_t)__cvta_generic_to_shared(dsm);
    const uint32_t wOff = (uint32_t)(cr*PITCH + cc)*2u;

    const int rA = lane & 15, cA = (lane & 16) >> 1;
    const int rB = (lane & 7) + ((lane & 16) >> 1), cB = lane & 8;
    const uint32_t offA = (uint32_t)(rA*PITCH + cA)*2u;
    const uint32_t offB = (uint32_t)(rB*PITCH + cB)*2u;

    float acc[4][4][4];
    #pragma unroll
    for (int i = 0; i < 4; i++)
        #pragma unroll
        for (int j = 0; j < 4; j++)
            #pragma unroll
            for (int r = 0; r < 4; r++) acc[i][j][r] = 0.f;

    const int NIT = QLEN/32;   // 16
    #pragma unroll
    for (int p = 0; p < 2; p++) {
        const uint32_t sa = sbase + p*TILEB + wOff;
        const uint32_t sb = sbase + BOFF + p*TILEB + wOff;
        CPA16(sa, Ag + p*32); CPA16(sa + 16u, Ag + p*32 + 8);
        CPA16(sb, Bg + p*32); CPA16(sb + 16u, Bg + p*32 + 8);
        CPCOMMIT();
    }

    for (int i = 0; i < NIT; i++) {
        if (i == NIT-1) { CPWAIT0(); } else { CPWAIT1(); }
        __syncthreads();
        const int st = i % 3;
        const uint32_t aBase = sbase + st*TILEB + (uint32_t)(wm*64)*PITCH*2u + offA;
        const uint32_t bBase = sbase + BOFF + st*TILEB + (uint32_t)(wn*32)*PITCH*2u + offB;
        #pragma unroll
        for (int ks = 0; ks < 32; ks += 16) {
            uint32_t a[4][4], bf[4][2];
            #pragma unroll
            for (int mt = 0; mt < 4; mt++)
                LDSM4(a[mt][0], a[mt][1], a[mt][2], a[mt][3],
                      aBase + (uint32_t)(mt*16)*PITCH*2u + ks*2u);
            #pragma unroll
            for (int p = 0; p < 2; p++)
                LDSM4(bf[2*p][0], bf[2*p][1], bf[2*p+1][0], bf[2*p+1][1],
                      bBase + (uint32_t)(p*16)*PITCH*2u + ks*2u);
            #pragma unroll
            for (int mt = 0; mt < 4; mt++)
                #pragma unroll
                for (int nt = 0; nt < 4; nt++)
                    mma_f16(acc[mt][nt], a[mt], bf[nt]);
        }
        if (i + 2 < NIT) {
            const int kc = (i+2)*32, s2 = (i+2) % 3;
            const uint32_t sa = sbase + s2*TILEB + wOff;
            const uint32_t sb = sbase + BOFF + s2*TILEB + wOff;
            CPA16(sa, Ag + kc); CPA16(sa + 16u, Ag + kc + 8);
            CPA16(sb, Bg + kc); CPA16(sb + 16u, Bg + kc + 8);
            CPCOMMIT();
        }
    }

    // fused epilogue: out = [c | c2q | c*c2q | c*q2c]
    const int nbase = n0 + wn*32;
    float2 gv[4];
    #pragma unroll
    for (int nt = 0; nt < 4; nt++)
        gv[nt] = *(const float2*)&g_q2c[b*H + nbase + nt*8 + 2*tig];
    #pragma unroll
    for (int mt = 0; mt < 4; mt++)
        #pragma unroll
        for (int r = 0; r < 2; r++) {
            int row = m0 + wm*64 + mt*16 + gid + 8*r;
            const float* crow = c + ((size_t)b*CLEN + row)*H;
            float* orow = out + ((size_t)b*CLEN + row)*(4*H);
            #pragma unroll
            for (int nt = 0; nt < 4; nt++) {
                int col = nbase + nt*8 + 2*tig;
                float2 cv = *(const float2*)&crow[col];
                float2 av = make_float2(acc[mt][nt][2*r], acc[mt][nt][2*r+1]);
                *(float2*)&orow[col]       = cv;
                *(float2*)&orow[H + col]   = av;
                *(float2*)&orow[2*H + col] = make_float2(cv.x*av.x, cv.y*av.y);
                *(float2*)&orow[3*H + col] = make_float2(cv.x*gv[nt].x, cv.y*gv[nt].y);
            }
        }
}

// ---------------------------------------------------------------------------
extern "C" void kernel_launch(void* const* d_in, const int* in_sizes, int n_in,
                              void* d_out, int out_size)
{
    const float* c    = (const float*)d_in[0];
    const float* q    = (const float*)d_in[1];
    const float* w_c  = (const float*)d_in[2];
    const float* b_c  = (const float*)d_in[3];
    const float* w_q  = (const float*)d_in[4];
    const float* b_q  = (const float*)d_in[5];
    const float* w_cq = (const float*)d_in[6];
    const float* b_cq = (const float*)d_in[7];
    float* out = (float*)d_out;

    cudaFuncSetAttribute(gemm1_f16, cudaFuncAttributeMaxDynamicSharedMemorySize, SMEMSZ);
    cudaFuncSetAttribute(gemm2_f16, cudaFuncAttributeMaxDynamicSharedMemorySize, SMEMSZ);

    {   // fp16 conversions
        size_t n4 = (size_t)B_*CLEN*(H/4) + (size_t)B_*QLEN*(H/4);
        prep_all<<<(unsigned)((n4 + 255)/256), 256>>>(
            (const float4*)c, (const float4*)q, (const float4*)w_cq);
    }
    {   // q^T fp16 for gemm2
        dim3 grid(QLEN/32, H/32, B_);
        qtrans_kernel<<<grid, dim3(32, 8)>>>(q);
    }
    {   // row dots
        int warps = B_*CLEN + B_*QLEN;
        uv_kernel<<<(warps*32 + 255)/256, 256>>>(c, q, w_c, b_c, w_q, b_q, b_cq);
    }
    {   // S = c.(q*w_cq)^T + v
        dim3 grid(QLEN/128, CLEN/128, B_);
        gemm1_f16<<<grid, 256, SMEMSZ>>>();
    }
    {   // row softmax -> fp16 probs
        int warps = B_*CLEN;
        softmax_kernel<<<(warps*32 + 255)/256, 256>>>();
    }
    bmz_kernel<<<B_, 1024>>>();
    {
        dim3 grid(32, B_);
        q2c_part<<<grid, 256>>>(c);
    }
    q2c_reduce<<<B_, 256>>>();
    {   // c2q + fused output
        dim3 grid(H/128, CLEN/128, B_);
        gemm2_f16<<<grid, 256, SMEMSZ>>>(c, out);
    }
}